// round 1
// baseline (speedup 1.0000x reference)
#include <cuda_runtime.h>
#include <math.h>

// Problem constants
#define B_   64
#define T_   32
#define H_   768
#define E_   8
#define NB_  2
#define DFF_ 3072
#define NBEAM 128   // B*NB

// Output packing offsets (float32 concatenation in tuple order)
#define OUT_MAIN 0
#define OUT_BS   (NBEAM * T_ * H_)        // 3145728
#define OUT_RT   (OUT_BS + NBEAM)         // +128
#define OUT_BI   (OUT_RT + NBEAM)         // +128
#define OUT_LOSS (OUT_BI + NBEAM)         // +128 -> scalar

// Scratch (device globals — allocation-free)
__device__ float g_scores[B_ * E_];
__device__ float g_weight[NBEAM];
__device__ int   g_expert[NBEAM];
__device__ float g_h[NBEAM * T_ * DFF_];   // ~50.3 MB intermediate

// ---------------------------------------------------------------------------
// Kernel 1: gating — per-batch mean over T, logits vs gate_w, softmax
// grid = 64 blocks, 256 threads
// ---------------------------------------------------------------------------
__global__ void gate_kernel(const float* __restrict__ x,
                            const float* __restrict__ gw)
{
    int b   = blockIdx.x;
    int tid = threadIdx.x;

    float part[E_];
#pragma unroll
    for (int e = 0; e < E_; e++) part[e] = 0.f;

    const float* xb = x + (size_t)b * T_ * H_;
    for (int h = tid; h < H_; h += 256) {
        float s = 0.f;
#pragma unroll 8
        for (int t = 0; t < T_; t++) s += xb[t * H_ + h];
        float avg = s * (1.f / (float)T_);
#pragma unroll
        for (int e = 0; e < E_; e++) part[e] += avg * gw[e * H_ + h];
    }

    // warp reduce
#pragma unroll
    for (int off = 16; off > 0; off >>= 1) {
#pragma unroll
        for (int e = 0; e < E_; e++)
            part[e] += __shfl_down_sync(0xffffffffu, part[e], off);
    }

    __shared__ float sacc[E_];
    if (tid < E_) sacc[tid] = 0.f;
    __syncthreads();
    if ((tid & 31) == 0) {
#pragma unroll
        for (int e = 0; e < E_; e++) atomicAdd(&sacc[e], part[e]);
    }
    __syncthreads();

    if (tid == 0) {
        float m = sacc[0];
#pragma unroll
        for (int e = 1; e < E_; e++) m = fmaxf(m, sacc[e]);
        float ex[E_], s = 0.f;
#pragma unroll
        for (int e = 0; e < E_; e++) { ex[e] = expf(sacc[e] - m); s += ex[e]; }
        float inv = 1.f / s;
#pragma unroll
        for (int e = 0; e < E_; e++) g_scores[b * E_ + e] = ex[e] * inv;
    }
}

// ---------------------------------------------------------------------------
// Kernel 2: finalize routing — top-2, importance loss, tail outputs
// 1 block, 128 threads
// ---------------------------------------------------------------------------
__global__ void finalize_kernel(float* __restrict__ out)
{
    int tid = threadIdx.x;

    __shared__ float simp[E_];
    if (tid < E_) {
        float s = 0.f;
        for (int b = 0; b < B_; b++) s += g_scores[b * E_ + tid];
        simp[tid] = s;
    }

    if (tid < B_) {
        int b = tid;
        float v0 = -1.f, v1 = -1.f;
        int   i0 = 0,    i1 = 0;
#pragma unroll
        for (int e = 0; e < E_; e++) {
            float v = g_scores[b * E_ + e];
            if (v > v0)      { v1 = v0; i1 = i0; v0 = v; i0 = e; }
            else if (v > v1) { v1 = v;  i1 = e; }
        }
        out[OUT_BS + 2 * b]     = v0;
        out[OUT_BS + 2 * b + 1] = v1;
        out[OUT_RT + 2 * b]     = (float)i0;
        out[OUT_RT + 2 * b + 1] = (float)i1;
        g_weight[2 * b]     = v0;
        g_weight[2 * b + 1] = v1;
        g_expert[2 * b]     = i0;
        g_expert[2 * b + 1] = i1;
    }

    out[OUT_BI + tid] = (float)tid;   // beam_idx = arange(128)

    __syncthreads();
    if (tid == 0) {
        float mean = 0.f;
#pragma unroll
        for (int e = 0; e < E_; e++) mean += simp[e];
        mean *= (1.f / (float)E_);
        float var = 0.f;
#pragma unroll
        for (int e = 0; e < E_; e++) { float d = simp[e] - mean; var += d * d; }
        var *= (1.f / (float)(E_ - 1));   // ddof=1
        out[OUT_LOSS] = var / (mean * mean);
    }
}

// ---------------------------------------------------------------------------
// GEMM tiles: BM=32, BN=64, BK=16, 128 threads, 4x4 microtile per thread
// A row-major [32, K], B row-major [N, K] (both K-contiguous -> "NT")
// smem staged transposed: As[k][m], Bs[k][n]
// ---------------------------------------------------------------------------
#define BK 16
#define APAD 4   // As row = 36 floats (144B, 16B aligned)
#define BPAD 4   // Bs row = 68 floats (272B, 16B aligned)

__device__ __forceinline__ float gelu_exact(float v)
{
    return 0.5f * v * (1.0f + erff(v * 0.70710678118654752f));
}

// Pass A: h[beam, t, f] = gelu(x[batch] @ w1[e]^T + b1[e]), tile over DFF
// grid = (DFF/64 = 48, 128 beams), 128 threads
__global__ void gemm1_kernel(const float* __restrict__ x,
                             const float* __restrict__ w1,
                             const float* __restrict__ b1)
{
    int beam = blockIdx.y;
    int e    = g_expert[beam];
    int nblk = blockIdx.x;                  // tile of 64 over DFF

    const float* A  = x  + (size_t)(beam >> 1) * T_ * H_;
    const float* Bw = w1 + ((size_t)e * DFF_ + (size_t)nblk * 64) * H_;

    __shared__ float As[BK][32 + APAD];
    __shared__ float Bs[BK][64 + BPAD];

    int tid = threadIdx.x;
    int ty = tid >> 4;          // 0..7
    int tx = tid & 15;          // 0..15

    float acc[4][4];
#pragma unroll
    for (int i = 0; i < 4; i++)
#pragma unroll
        for (int j = 0; j < 4; j++) acc[i][j] = 0.f;

    for (int k0 = 0; k0 < H_; k0 += BK) {
        // load A tile 32x16 (128 float4, one per thread), store transposed
        {
            int row = tid >> 2, c4 = (tid & 3) * 4;
            float4 v = *(const float4*)(A + row * H_ + k0 + c4);
            As[c4 + 0][row] = v.x; As[c4 + 1][row] = v.y;
            As[c4 + 2][row] = v.z; As[c4 + 3][row] = v.w;
        }
        // load B tile 64x16 (256 float4, two per thread)
#pragma unroll
        for (int i = 0; i < 2; i++) {
            int idx = tid + i * 128;
            int row = idx >> 2, c4 = (idx & 3) * 4;
            float4 v = *(const float4*)(Bw + row * H_ + k0 + c4);
            Bs[c4 + 0][row] = v.x; Bs[c4 + 1][row] = v.y;
            Bs[c4 + 2][row] = v.z; Bs[c4 + 3][row] = v.w;
        }
        __syncthreads();

#pragma unroll
        for (int k = 0; k < BK; k++) {
            float4 av = *(const float4*)&As[k][ty * 4];
            float4 bv = *(const float4*)&Bs[k][tx * 4];
            float a[4] = { av.x, av.y, av.z, av.w };
            float b[4] = { bv.x, bv.y, bv.z, bv.w };
#pragma unroll
            for (int i = 0; i < 4; i++)
#pragma unroll
                for (int j = 0; j < 4; j++)
                    acc[i][j] = fmaf(a[i], b[j], acc[i][j]);
        }
        __syncthreads();
    }

    // epilogue: +b1, gelu, store to g_h
    int fbase = nblk * 64 + tx * 4;
    float bb[4];
#pragma unroll
    for (int j = 0; j < 4; j++) bb[j] = b1[e * DFF_ + fbase + j];

    float* hp = g_h + (size_t)beam * T_ * DFF_;
#pragma unroll
    for (int i = 0; i < 4; i++) {
        int t = ty * 4 + i;
        float4 o;
        o.x = gelu_exact(acc[i][0] + bb[0]);
        o.y = gelu_exact(acc[i][1] + bb[1]);
        o.z = gelu_exact(acc[i][2] + bb[2]);
        o.w = gelu_exact(acc[i][3] + bb[3]);
        *(float4*)(hp + (size_t)t * DFF_ + fbase) = o;
    }
}

// Pass B: out[beam, t, hh] = weight * (h[beam] @ w2[e]^T + b2[e])
// grid = (H/64 = 12, 128 beams), 128 threads
__global__ void gemm2_kernel(const float* __restrict__ w2,
                             const float* __restrict__ b2,
                             float* __restrict__ out)
{
    int beam = blockIdx.y;
    int e    = g_expert[beam];
    float wgt = g_weight[beam];
    int nblk = blockIdx.x;                  // tile of 64 over H

    const float* A  = g_h + (size_t)beam * T_ * DFF_;
    const float* Bw = w2 + ((size_t)e * H_ + (size_t)nblk * 64) * DFF_;

    __shared__ float As[BK][32 + APAD];
    __shared__ float Bs[BK][64 + BPAD];

    int tid = threadIdx.x;
    int ty = tid >> 4;
    int tx = tid & 15;

    float acc[4][4];
#pragma unroll
    for (int i = 0; i < 4; i++)
#pragma unroll
        for (int j = 0; j < 4; j++) acc[i][j] = 0.f;

    for (int k0 = 0; k0 < DFF_; k0 += BK) {
        {
            int row = tid >> 2, c4 = (tid & 3) * 4;
            float4 v = *(const float4*)(A + (size_t)row * DFF_ + k0 + c4);
            As[c4 + 0][row] = v.x; As[c4 + 1][row] = v.y;
            As[c4 + 2][row] = v.z; As[c4 + 3][row] = v.w;
        }
#pragma unroll
        for (int i = 0; i < 2; i++) {
            int idx = tid + i * 128;
            int row = idx >> 2, c4 = (idx & 3) * 4;
            float4 v = *(const float4*)(Bw + (size_t)row * DFF_ + k0 + c4);
            Bs[c4 + 0][row] = v.x; Bs[c4 + 1][row] = v.y;
            Bs[c4 + 2][row] = v.z; Bs[c4 + 3][row] = v.w;
        }
        __syncthreads();

#pragma unroll
        for (int k = 0; k < BK; k++) {
            float4 av = *(const float4*)&As[k][ty * 4];
            float4 bv = *(const float4*)&Bs[k][tx * 4];
            float a[4] = { av.x, av.y, av.z, av.w };
            float b[4] = { bv.x, bv.y, bv.z, bv.w };
#pragma unroll
            for (int i = 0; i < 4; i++)
#pragma unroll
                for (int j = 0; j < 4; j++)
                    acc[i][j] = fmaf(a[i], b[j], acc[i][j]);
        }
        __syncthreads();
    }

    int hbase = nblk * 64 + tx * 4;
    float bb[4];
#pragma unroll
    for (int j = 0; j < 4; j++) bb[j] = b2[e * H_ + hbase + j];

    float* op = out + OUT_MAIN + (size_t)beam * T_ * H_;
#pragma unroll
    for (int i = 0; i < 4; i++) {
        int t = ty * 4 + i;
        float4 o;
        o.x = (acc[i][0] + bb[0]) * wgt;
        o.y = (acc[i][1] + bb[1]) * wgt;
        o.z = (acc[i][2] + bb[2]) * wgt;
        o.w = (acc[i][3] + bb[3]) * wgt;
        *(float4*)(op + (size_t)t * H_ + hbase) = o;
    }
}

// ---------------------------------------------------------------------------
extern "C" void kernel_launch(void* const* d_in, const int* in_sizes, int n_in,
                              void* d_out, int out_size)
{
    (void)in_sizes; (void)n_in; (void)out_size;
    const float* x      = (const float*)d_in[0];
    const float* gate_w = (const float*)d_in[1];
    const float* w1     = (const float*)d_in[2];
    const float* b1     = (const float*)d_in[3];
    const float* w2     = (const float*)d_in[4];
    const float* b2     = (const float*)d_in[5];
    float* out = (float*)d_out;

    gate_kernel<<<B_, 256>>>(x, gate_w);
    finalize_kernel<<<1, 128>>>(out);
    gemm1_kernel<<<dim3(DFF_ / 64, NBEAM), 128>>>(x, w1, b1);
    gemm2_kernel<<<dim3(H_ / 64, NBEAM), 128>>>(w2, b2, out);
}

// round 4
// speedup vs baseline: 2.4331x; 2.4331x over previous
#include <cuda_runtime.h>
#include <math.h>
#include <stdint.h>

// Problem constants
#define B_   64
#define T_   32
#define H_   768
#define E_   8
#define NB_  2
#define DFF_ 3072
#define NBEAM 128   // B*NB

// Output packing offsets (float32 concatenation in tuple order)
#define OUT_MAIN 0
#define OUT_BS   (NBEAM * T_ * H_)        // 3145728
#define OUT_RT   (OUT_BS + NBEAM)
#define OUT_BI   (OUT_RT + NBEAM)
#define OUT_LOSS (OUT_BI + NBEAM)

// Scratch (device globals — allocation-free)
__device__ float g_scores[B_ * E_];
__device__ float g_weight[NBEAM];
__device__ int   g_expert[NBEAM];
__device__ int   g_perm[NBEAM];
__device__ int   g_off[E_ + 1];
__device__ float g_h[(size_t)NBEAM * T_ * DFF_];   // ~50.3 MB intermediate

// ---------------------------------------------------------------------------
// helpers
// ---------------------------------------------------------------------------
__device__ __forceinline__ uint32_t smem_u32(const void* p) {
    uint32_t a;
    asm("{ .reg .u64 t; cvta.to.shared.u64 t, %1; cvt.u32.u64 %0, t; }"
        : "=r"(a) : "l"(p));
    return a;
}

__device__ __forceinline__ void cp16(uint32_t smem_addr, const void* gptr) {
    asm volatile("cp.async.cg.shared.global [%0], [%1], 16;"
                 :: "r"(smem_addr), "l"(gptr));
}
#define CP_COMMIT() asm volatile("cp.async.commit_group;" ::: "memory")
#define CP_WAIT0()  asm volatile("cp.async.wait_group 0;" ::: "memory")

__device__ __forceinline__ uint32_t f2tf32(float f) {
    uint32_t r;
    asm("cvt.rna.tf32.f32 %0, %1;" : "=r"(r) : "f"(f));
    return r;
}

__device__ __forceinline__ void mma1688(float* c, const uint32_t* a, const uint32_t* b) {
    asm volatile(
        "mma.sync.aligned.m16n8k8.row.col.f32.tf32.tf32.f32 "
        "{%0,%1,%2,%3}, {%4,%5,%6,%7}, {%8,%9}, {%0,%1,%2,%3};"
        : "+f"(c[0]), "+f"(c[1]), "+f"(c[2]), "+f"(c[3])
        : "r"(a[0]), "r"(a[1]), "r"(a[2]), "r"(a[3]), "r"(b[0]), "r"(b[1]));
}

__device__ __forceinline__ float gelu_exact(float v) {
    return 0.5f * v * (1.0f + erff(v * 0.70710678118654752f));
}

// ---------------------------------------------------------------------------
// Kernel 1: gating — per-batch mean over T, logits, softmax
// ---------------------------------------------------------------------------
__global__ void gate_kernel(const float* __restrict__ x,
                            const float* __restrict__ gw)
{
    int b = blockIdx.x, tid = threadIdx.x;
    float part[E_];
#pragma unroll
    for (int e = 0; e < E_; e++) part[e] = 0.f;
    const float* xb = x + (size_t)b * T_ * H_;
    for (int h = tid; h < H_; h += 256) {
        float s = 0.f;
#pragma unroll 8
        for (int t = 0; t < T_; t++) s += xb[t * H_ + h];
        float avg = s * (1.f / (float)T_);
#pragma unroll
        for (int e = 0; e < E_; e++) part[e] += avg * gw[e * H_ + h];
    }
#pragma unroll
    for (int off = 16; off > 0; off >>= 1)
#pragma unroll
        for (int e = 0; e < E_; e++)
            part[e] += __shfl_down_sync(0xffffffffu, part[e], off);
    __shared__ float sacc[E_];
    if (tid < E_) sacc[tid] = 0.f;
    __syncthreads();
    if ((tid & 31) == 0)
#pragma unroll
        for (int e = 0; e < E_; e++) atomicAdd(&sacc[e], part[e]);
    __syncthreads();
    if (tid == 0) {
        float m = sacc[0];
#pragma unroll
        for (int e = 1; e < E_; e++) m = fmaxf(m, sacc[e]);
        float ex[E_], s = 0.f;
#pragma unroll
        for (int e = 0; e < E_; e++) { ex[e] = expf(sacc[e] - m); s += ex[e]; }
        float inv = 1.f / s;
#pragma unroll
        for (int e = 0; e < E_; e++) g_scores[b * E_ + e] = ex[e] * inv;
    }
}

// ---------------------------------------------------------------------------
// Kernel 2: finalize routing — top-2, loss, tail outputs, expert grouping
// ---------------------------------------------------------------------------
__global__ void finalize_kernel(float* __restrict__ out)
{
    int tid = threadIdx.x;
    __shared__ float simp[E_];
    if (tid < E_) {
        float s = 0.f;
        for (int b = 0; b < B_; b++) s += g_scores[b * E_ + tid];
        simp[tid] = s;
    }
    if (tid < B_) {
        int b = tid;
        float v0 = -1.f, v1 = -1.f; int i0 = 0, i1 = 0;
#pragma unroll
        for (int e = 0; e < E_; e++) {
            float v = g_scores[b * E_ + e];
            if (v > v0)      { v1 = v0; i1 = i0; v0 = v; i0 = e; }
            else if (v > v1) { v1 = v;  i1 = e; }
        }
        out[OUT_BS + 2 * b]     = v0;
        out[OUT_BS + 2 * b + 1] = v1;
        out[OUT_RT + 2 * b]     = (float)i0;
        out[OUT_RT + 2 * b + 1] = (float)i1;
        g_weight[2 * b] = v0;  g_weight[2 * b + 1] = v1;
        g_expert[2 * b] = i0;  g_expert[2 * b + 1] = i1;
    }
    out[OUT_BI + tid] = (float)tid;
    __syncthreads();
    if (tid == 0) {
        float mean = 0.f;
#pragma unroll
        for (int e = 0; e < E_; e++) mean += simp[e];
        mean *= (1.f / (float)E_);
        float var = 0.f;
#pragma unroll
        for (int e = 0; e < E_; e++) { float d = simp[e] - mean; var += d * d; }
        var *= (1.f / (float)(E_ - 1));
        out[OUT_LOSS] = var / (mean * mean);
        int pos = 0;
        for (int e = 0; e < E_; e++) {
            g_off[e] = pos;
            for (int bm = 0; bm < NBEAM; bm++)
                if (g_expert[bm] == e) g_perm[pos++] = bm;
        }
        g_off[E_] = pos;
    }
}

// ---------------------------------------------------------------------------
// Unified tf32 mma.sync GEMM
// CTA: M=128 weight-rows x N=128 tokens (4 beams), BK=16, 256 thr, 8 warps 4x2
// warp tile 32(M) x 64(N): 2 m-subtiles x 8 n-subtiles of m16n8k8
// A = W[e] rows (K-major), B = tokens (K-major) -> mma row.col
// G1: Bsrc = x (host arg), dst = g_h (device symbol), epi = gelu(acc + b1)
// G2: Bsrc = g_h (device symbol!), dst = out,          epi = (acc + b2)*wgt
// NOTE: g_h must be referenced from DEVICE code only (host sees shadow).
// ---------------------------------------------------------------------------
#define BM 128
#define BN 128
#define BKT 16
#define STR 20                  // smem row stride (floats); bank-conflict-free
#define ABUF (BM * STR)         // floats per A buffer
#define BBUF (BN * STR)
#define SMEM_FLOATS (2 * (ABUF + BBUF))

template<int KDIM, bool G1>
__global__ void __launch_bounds__(256)
moe_gemm(const float* __restrict__ W, const float* __restrict__ bias,
         const float* __restrict__ xin, float* __restrict__ dst)
{
    const int e = blockIdx.y;
    const int cnt = g_off[e + 1] - g_off[e];
    const int chunk = blockIdx.z;
    if (chunk * 4 >= cnt) return;
    const int m0 = blockIdx.x * BM;
    const int MD = G1 ? DFF_ : H_;

    // device-side source selection (g_h is a __device__ symbol)
    const float* Bsrc = G1 ? xin : (const float*)g_h;

    extern __shared__ __align__(16) float smem[];
    float* As = smem;               // 2 x ABUF
    float* Bs = smem + 2 * ABUF;    // 2 x BBUF

    const int tid = threadIdx.x;
    const int wid = tid >> 5, lane = tid & 31;
    const int wm = wid >> 1, wn = wid & 1;
    const int lg = lane >> 2;       // groupID 0..7
    const int lt = lane & 3;        // threadInGroup 0..3

    int beamv[4];
#pragma unroll
    for (int j = 0; j < 4; j++) {
        int idx = chunk * 4 + j;
        beamv[j] = (idx < cnt) ? g_perm[g_off[e] + idx] : -1;
    }

    // per-thread cp.async coordinates (2 A chunks + 2 B chunks of 16B)
    const float* wbase = W + (size_t)e * MD * KDIM;
    const float* agp[2];  uint32_t asp[2];
    const float* bgp[2];  uint32_t bsp[2];
#pragma unroll
    for (int t = 0; t < 2; t++) {
        int id = tid + 256 * t;
        int row = id >> 2, c = id & 3;
        agp[t] = wbase + (size_t)(m0 + row) * KDIM + c * 4;
        asp[t] = smem_u32(As) + (uint32_t)(row * STR + c * 4) * 4u;
        int tok = row;                     // 0..127
        int slot = tok >> 5, tt = tok & 31;
        int bm = beamv[slot]; if (bm < 0) bm = beamv[0];
        int bi = G1 ? (bm >> 1) : bm;
        bgp[t] = Bsrc + ((size_t)bi * T_ + tt) * KDIM + c * 4;
        bsp[t] = smem_u32(Bs) + (uint32_t)(tok * STR + c * 4) * 4u;
    }

    const uint32_t ABUFB = ABUF * 4u, BBUFB = BBUF * 4u;
    const int KT = KDIM / BKT;

    // prologue
    {
#pragma unroll
        for (int t = 0; t < 2; t++) cp16(asp[t], agp[t]);
#pragma unroll
        for (int t = 0; t < 2; t++) cp16(bsp[t], bgp[t]);
        CP_COMMIT();
    }

    float acc[2][8][4];
#pragma unroll
    for (int i = 0; i < 2; i++)
#pragma unroll
        for (int j = 0; j < 8; j++)
#pragma unroll
            for (int r = 0; r < 4; r++) acc[i][j][r] = 0.f;

#pragma unroll 1
    for (int kt = 0; kt < KT; kt++) {
        CP_WAIT0();
        __syncthreads();
        int b = kt & 1;
        if (kt + 1 < KT) {
            uint32_t ao = (uint32_t)((kt + 1) & 1) * ABUFB;
            uint32_t bo = (uint32_t)((kt + 1) & 1) * BBUFB;
            int koff = (kt + 1) * BKT;
#pragma unroll
            for (int t = 0; t < 2; t++) cp16(asp[t] + ao, agp[t] + koff);
#pragma unroll
            for (int t = 0; t < 2; t++) cp16(bsp[t] + bo, bgp[t] + koff);
            CP_COMMIT();
        }

        const float* Ab = As + b * ABUF;
        const float* Bb = Bs + b * BBUF;
#pragma unroll
        for (int ks = 0; ks < 2; ks++) {
            const int kc = ks * 8 + lt;
            uint32_t afr[2][4], bfr[8][2];
#pragma unroll
            for (int i = 0; i < 2; i++) {
                int r = wm * 32 + i * 16 + lg;
                afr[i][0] = f2tf32(Ab[r * STR + kc]);
                afr[i][1] = f2tf32(Ab[(r + 8) * STR + kc]);
                afr[i][2] = f2tf32(Ab[r * STR + kc + 4]);
                afr[i][3] = f2tf32(Ab[(r + 8) * STR + kc + 4]);
            }
#pragma unroll
            for (int j = 0; j < 8; j++) {
                int n = wn * 64 + j * 8 + lg;
                bfr[j][0] = f2tf32(Bb[n * STR + kc]);
                bfr[j][1] = f2tf32(Bb[n * STR + kc + 4]);
            }
#pragma unroll
            for (int i = 0; i < 2; i++)
#pragma unroll
                for (int j = 0; j < 8; j++)
                    mma1688(acc[i][j], afr[i], bfr[j]);
        }
        __syncthreads();
    }

    // epilogue
#pragma unroll
    for (int i = 0; i < 2; i++) {
        int r0 = wm * 32 + i * 16 + lg;
        int r1 = r0 + 8;
        int gm0 = m0 + r0, gm1 = m0 + r1;
        float bi0 = bias[e * MD + gm0];
        float bi1 = bias[e * MD + gm1];
#pragma unroll
        for (int j = 0; j < 8; j++) {
            int tok = wn * 64 + j * 8 + lt * 2;
            int slot = tok >> 5;
            int bm = beamv[slot];
            if (bm < 0) continue;
            int tt = tok & 31;
            if (G1) {
                float* p = g_h + ((size_t)bm * T_ + tt) * DFF_;
                p[gm0]         = gelu_exact(acc[i][j][0] + bi0);
                p[DFF_ + gm0]  = gelu_exact(acc[i][j][1] + bi0);
                p[gm1]         = gelu_exact(acc[i][j][2] + bi1);
                p[DFF_ + gm1]  = gelu_exact(acc[i][j][3] + bi1);
            } else {
                float w = g_weight[bm];
                float* p = dst + OUT_MAIN + ((size_t)bm * T_ + tt) * H_;
                p[gm0]       = (acc[i][j][0] + bi0) * w;
                p[H_ + gm0]  = (acc[i][j][1] + bi0) * w;
                p[gm1]       = (acc[i][j][2] + bi1) * w;
                p[H_ + gm1]  = (acc[i][j][3] + bi1) * w;
            }
        }
    }
}

// ---------------------------------------------------------------------------
extern "C" void kernel_launch(void* const* d_in, const int* in_sizes, int n_in,
                              void* d_out, int out_size)
{
    (void)in_sizes; (void)n_in; (void)out_size;
    const float* x      = (const float*)d_in[0];
    const float* gate_w = (const float*)d_in[1];
    const float* w1     = (const float*)d_in[2];
    const float* b1     = (const float*)d_in[3];
    const float* w2     = (const float*)d_in[4];
    const float* b2     = (const float*)d_in[5];
    float* out = (float*)d_out;

    const int smem_bytes = SMEM_FLOATS * 4;   // 40960

    gate_kernel<<<B_, 256>>>(x, gate_w);
    finalize_kernel<<<1, 128>>>(out);
    // h = gelu(x @ W1^T + b1)   (per-expert, beams grouped 4 per CTA)
    moe_gemm<H_, true><<<dim3(DFF_ / BM, E_, 32), 256, smem_bytes>>>(w1, b1, x, nullptr);
    // out = (h @ W2^T + b2) * weight   (B operand = g_h, resolved device-side)
    moe_gemm<DFF_, false><<<dim3(H_ / BM, E_, 32), 256, smem_bytes>>>(w2, b2, nullptr, out);
}

// round 5
// speedup vs baseline: 2.4624x; 1.0120x over previous
#include <cuda_runtime.h>
#include <math.h>
#include <stdint.h>

// Problem constants
#define B_   64
#define T_   32
#define H_   768
#define E_   8
#define NB_  2
#define DFF_ 3072
#define NBEAM 128   // B*NB

// Output packing offsets (float32 concatenation in tuple order)
#define OUT_MAIN 0
#define OUT_BS   (NBEAM * T_ * H_)        // 3145728
#define OUT_RT   (OUT_BS + NBEAM)
#define OUT_BI   (OUT_RT + NBEAM)
#define OUT_LOSS (OUT_BI + NBEAM)

// Scratch (device globals — allocation-free)
__device__ float g_scores[B_ * E_];
__device__ float g_weight[NBEAM];
__device__ int   g_expert[NBEAM];
__device__ int   g_perm[NBEAM];
__device__ int   g_off[E_ + 1];
__device__ float g_h[(size_t)NBEAM * T_ * DFF_];   // ~50.3 MB intermediate

// ---------------------------------------------------------------------------
// helpers
// ---------------------------------------------------------------------------
__device__ __forceinline__ uint32_t smem_u32(const void* p) {
    uint32_t a;
    asm("{ .reg .u64 t; cvta.to.shared.u64 t, %1; cvt.u32.u64 %0, t; }"
        : "=r"(a) : "l"(p));
    return a;
}

__device__ __forceinline__ void cp16(uint32_t smem_addr, const void* gptr) {
    asm volatile("cp.async.cg.shared.global [%0], [%1], 16;"
                 :: "r"(smem_addr), "l"(gptr));
}
#define CP_COMMIT() asm volatile("cp.async.commit_group;" ::: "memory")
#define CP_WAIT1()  asm volatile("cp.async.wait_group 1;" ::: "memory")

__device__ __forceinline__ uint32_t f2tf32(float f) {
    uint32_t r;
    asm("cvt.rna.tf32.f32 %0, %1;" : "=r"(r) : "f"(f));
    return r;
}

__device__ __forceinline__ void mma1688(float* c, const uint32_t* a, const uint32_t* b) {
    asm volatile(
        "mma.sync.aligned.m16n8k8.row.col.f32.tf32.tf32.f32 "
        "{%0,%1,%2,%3}, {%4,%5,%6,%7}, {%8,%9}, {%0,%1,%2,%3};"
        : "+f"(c[0]), "+f"(c[1]), "+f"(c[2]), "+f"(c[3])
        : "r"(a[0]), "r"(a[1]), "r"(a[2]), "r"(a[3]), "r"(b[0]), "r"(b[1]));
}

__device__ __forceinline__ float gelu_exact(float v) {
    return 0.5f * v * (1.0f + erff(v * 0.70710678118654752f));
}

// ---------------------------------------------------------------------------
// Kernel 1: gating — per-batch mean over T, logits, softmax
// ---------------------------------------------------------------------------
__global__ void gate_kernel(const float* __restrict__ x,
                            const float* __restrict__ gw)
{
    int b = blockIdx.x, tid = threadIdx.x;
    float part[E_];
#pragma unroll
    for (int e = 0; e < E_; e++) part[e] = 0.f;
    const float* xb = x + (size_t)b * T_ * H_;
    for (int h = tid; h < H_; h += 256) {
        float s = 0.f;
#pragma unroll 8
        for (int t = 0; t < T_; t++) s += xb[t * H_ + h];
        float avg = s * (1.f / (float)T_);
#pragma unroll
        for (int e = 0; e < E_; e++) part[e] += avg * gw[e * H_ + h];
    }
#pragma unroll
    for (int off = 16; off > 0; off >>= 1)
#pragma unroll
        for (int e = 0; e < E_; e++)
            part[e] += __shfl_down_sync(0xffffffffu, part[e], off);
    __shared__ float sacc[E_];
    if (tid < E_) sacc[tid] = 0.f;
    __syncthreads();
    if ((tid & 31) == 0)
#pragma unroll
        for (int e = 0; e < E_; e++) atomicAdd(&sacc[e], part[e]);
    __syncthreads();
    if (tid == 0) {
        float m = sacc[0];
#pragma unroll
        for (int e = 1; e < E_; e++) m = fmaxf(m, sacc[e]);
        float ex[E_], s = 0.f;
#pragma unroll
        for (int e = 0; e < E_; e++) { ex[e] = expf(sacc[e] - m); s += ex[e]; }
        float inv = 1.f / s;
#pragma unroll
        for (int e = 0; e < E_; e++) g_scores[b * E_ + e] = ex[e] * inv;
    }
}

// ---------------------------------------------------------------------------
// Kernel 2: finalize routing — top-2, loss, tail outputs, expert grouping
// ---------------------------------------------------------------------------
__global__ void finalize_kernel(float* __restrict__ out)
{
    int tid = threadIdx.x;
    __shared__ float simp[E_];
    if (tid < E_) {
        float s = 0.f;
        for (int b = 0; b < B_; b++) s += g_scores[b * E_ + tid];
        simp[tid] = s;
    }
    if (tid < B_) {
        int b = tid;
        float v0 = -1.f, v1 = -1.f; int i0 = 0, i1 = 0;
#pragma unroll
        for (int e = 0; e < E_; e++) {
            float v = g_scores[b * E_ + e];
            if (v > v0)      { v1 = v0; i1 = i0; v0 = v; i0 = e; }
            else if (v > v1) { v1 = v;  i1 = e; }
        }
        out[OUT_BS + 2 * b]     = v0;
        out[OUT_BS + 2 * b + 1] = v1;
        out[OUT_RT + 2 * b]     = (float)i0;
        out[OUT_RT + 2 * b + 1] = (float)i1;
        g_weight[2 * b] = v0;  g_weight[2 * b + 1] = v1;
        g_expert[2 * b] = i0;  g_expert[2 * b + 1] = i1;
    }
    out[OUT_BI + tid] = (float)tid;
    __syncthreads();
    if (tid == 0) {
        float mean = 0.f;
#pragma unroll
        for (int e = 0; e < E_; e++) mean += simp[e];
        mean *= (1.f / (float)E_);
        float var = 0.f;
#pragma unroll
        for (int e = 0; e < E_; e++) { float d = simp[e] - mean; var += d * d; }
        var *= (1.f / (float)(E_ - 1));
        out[OUT_LOSS] = var / (mean * mean);
        int pos = 0;
        for (int e = 0; e < E_; e++) {
            g_off[e] = pos;
            for (int bm = 0; bm < NBEAM; bm++)
                if (g_expert[bm] == e) g_perm[pos++] = bm;
        }
        g_off[E_] = pos;
    }
}

// ---------------------------------------------------------------------------
// Unified tf32 mma.sync GEMM — occupancy-tuned
// CTA: M=64 weight-rows x N=128 tokens (4 beams), BK=16, 256 thr, 8 warps
// warps: wm=4 (16 rows each) x wn=2 (64 tokens each)
// warp tile 16(M) x 64(N): 1 m-sub x 8 n-sub of m16n8k8; acc = 32 regs
// 3-stage cp.async pipeline, wait_group 1
// ---------------------------------------------------------------------------
#define BM 64
#define BN 128
#define BKT 16
#define STG 3
#define STR 20                  // smem row stride (floats); conflict-free
#define ABUF (BM * STR)         // 1280 floats / stage
#define BBUF (BN * STR)         // 2560 floats / stage
#define SMEM_FLOATS (STG * (ABUF + BBUF))   // 11520 floats = 46080 B

template<int KDIM, bool G1>
__global__ void __launch_bounds__(256, 3)
moe_gemm(const float* __restrict__ W, const float* __restrict__ bias,
         const float* __restrict__ xin, float* __restrict__ dst)
{
    const int e = blockIdx.y;
    const int cnt = g_off[e + 1] - g_off[e];
    const int chunk = blockIdx.z;
    if (chunk * 4 >= cnt) return;
    const int m0 = blockIdx.x * BM;
    const int MD = G1 ? DFF_ : H_;

    const float* Bsrc = G1 ? xin : (const float*)g_h;   // device-side select

    extern __shared__ __align__(16) float smem[];
    float* As = smem;                 // STG x ABUF
    float* Bs = smem + STG * ABUF;    // STG x BBUF

    const int tid = threadIdx.x;
    const int wid = tid >> 5, lane = tid & 31;
    const int wm = wid >> 1, wn = wid & 1;
    const int lg = lane >> 2;       // 0..7
    const int lt = lane & 3;        // 0..3

    int beamv[4];
#pragma unroll
    for (int j = 0; j < 4; j++) {
        int idx = chunk * 4 + j;
        beamv[j] = (idx < cnt) ? g_perm[g_off[e] + idx] : -1;
    }

    // cp.async coords: A 64x16 = 256 float4 (1/thread); B 128x16 = 512 (2/thread)
    const float* wbase = W + (size_t)e * MD * KDIM;
    const float* agp;  uint32_t asp;
    const float* bgp[2]; uint32_t bsp[2];
    {
        int row = tid >> 2, c = tid & 3;
        agp = wbase + (size_t)(m0 + row) * KDIM + c * 4;
        asp = smem_u32(As) + (uint32_t)(row * STR + c * 4) * 4u;
    }
#pragma unroll
    for (int t = 0; t < 2; t++) {
        int id = tid + 256 * t;
        int tok = id >> 2, c = id & 3;
        int slot = tok >> 5, tt = tok & 31;
        int bm = beamv[slot]; if (bm < 0) bm = beamv[0];
        int bi = G1 ? (bm >> 1) : bm;
        bgp[t] = Bsrc + ((size_t)bi * T_ + tt) * KDIM + c * 4;
        bsp[t] = smem_u32(Bs) + (uint32_t)(tok * STR + c * 4) * 4u;
    }

    const uint32_t ABUFB = ABUF * 4u, BBUFB = BBUF * 4u;
    const int KT = KDIM / BKT;

    // prologue: stages 0,1
#pragma unroll
    for (int s = 0; s < 2; s++) {
        cp16(asp + s * ABUFB, agp + s * BKT);
#pragma unroll
        for (int t = 0; t < 2; t++)
            cp16(bsp[t] + s * BBUFB, bgp[t] + s * BKT);
        CP_COMMIT();
    }

    float acc[8][4];
#pragma unroll
    for (int j = 0; j < 8; j++)
#pragma unroll
        for (int r = 0; r < 4; r++) acc[j][r] = 0.f;

    int buf = 0, pbuf = 2;   // compute buffer, prefetch buffer
#pragma unroll 1
    for (int kt = 0; kt < KT; kt++) {
        CP_WAIT1();
        __syncthreads();
        if (kt + 2 < KT) {
            int koff = (kt + 2) * BKT;
            cp16(asp + pbuf * ABUFB, agp + koff);
#pragma unroll
            for (int t = 0; t < 2; t++)
                cp16(bsp[t] + pbuf * BBUFB, bgp[t] + koff);
        }
        CP_COMMIT();

        const float* Ab = As + buf * ABUF;
        const float* Bb = Bs + buf * BBUF;
#pragma unroll
        for (int ks = 0; ks < 2; ks++) {
            const int kc = ks * 8 + lt;
            uint32_t afr[4], bfr[8][2];
            {
                int r = wm * 16 + lg;
                afr[0] = f2tf32(Ab[r * STR + kc]);
                afr[1] = f2tf32(Ab[(r + 8) * STR + kc]);
                afr[2] = f2tf32(Ab[r * STR + kc + 4]);
                afr[3] = f2tf32(Ab[(r + 8) * STR + kc + 4]);
            }
#pragma unroll
            for (int j = 0; j < 8; j++) {
                int n = wn * 64 + j * 8 + lg;
                bfr[j][0] = f2tf32(Bb[n * STR + kc]);
                bfr[j][1] = f2tf32(Bb[n * STR + kc + 4]);
            }
#pragma unroll
            for (int j = 0; j < 8; j++)
                mma1688(acc[j], afr, bfr[j]);
        }
        buf = (buf == STG - 1) ? 0 : buf + 1;
        pbuf = (pbuf == STG - 1) ? 0 : pbuf + 1;
    }

    // epilogue
    {
        int r0 = wm * 16 + lg;
        int r1 = r0 + 8;
        int gm0 = m0 + r0, gm1 = m0 + r1;
        float bi0 = bias[e * MD + gm0];
        float bi1 = bias[e * MD + gm1];
#pragma unroll
        for (int j = 0; j < 8; j++) {
            int tok = wn * 64 + j * 8 + lt * 2;
            int slot = tok >> 5;
            int bm = beamv[slot];
            if (bm < 0) continue;
            int tt = tok & 31;
            if (G1) {
                float* p = g_h + ((size_t)bm * T_ + tt) * DFF_;
                p[gm0]         = gelu_exact(acc[j][0] + bi0);
                p[DFF_ + gm0]  = gelu_exact(acc[j][1] + bi0);
                p[gm1]         = gelu_exact(acc[j][2] + bi1);
                p[DFF_ + gm1]  = gelu_exact(acc[j][3] + bi1);
            } else {
                float w = g_weight[bm];
                float* p = dst + OUT_MAIN + ((size_t)bm * T_ + tt) * H_;
                p[gm0]       = (acc[j][0] + bi0) * w;
                p[H_ + gm0]  = (acc[j][1] + bi0) * w;
                p[gm1]       = (acc[j][2] + bi1) * w;
                p[H_ + gm1]  = (acc[j][3] + bi1) * w;
            }
        }
    }
}

// ---------------------------------------------------------------------------
extern "C" void kernel_launch(void* const* d_in, const int* in_sizes, int n_in,
                              void* d_out, int out_size)
{
    (void)in_sizes; (void)n_in; (void)out_size;
    const float* x      = (const float*)d_in[0];
    const float* gate_w = (const float*)d_in[1];
    const float* w1     = (const float*)d_in[2];
    const float* b1     = (const float*)d_in[3];
    const float* w2     = (const float*)d_in[4];
    const float* b2     = (const float*)d_in[5];
    float* out = (float*)d_out;

    const int smem_bytes = SMEM_FLOATS * 4;   // 46080

    gate_kernel<<<B_, 256>>>(x, gate_w);
    finalize_kernel<<<1, 128>>>(out);
    // h = gelu(x @ W1^T + b1)
    moe_gemm<H_, true><<<dim3(DFF_ / BM, E_, 32), 256, smem_bytes>>>(w1, b1, x, nullptr);
    // out = (h @ W2^T + b2) * weight
    moe_gemm<DFF_, false><<<dim3(H_ / BM, E_, 32), 256, smem_bytes>>>(w2, b2, nullptr, out);
}

// round 6
// speedup vs baseline: 2.5234x; 1.0248x over previous
#include <cuda_runtime.h>
#include <math.h>
#include <stdint.h>

// Problem constants
#define B_   64
#define T_   32
#define H_   768
#define E_   8
#define NB_  2
#define DFF_ 3072
#define NBEAM 128   // B*NB
#define SPLIT 4     // split-K factor for GEMM2

// Output packing offsets (float32 concatenation in tuple order)
#define OUT_MAIN 0
#define OUT_BS   (NBEAM * T_ * H_)        // 3145728
#define OUT_RT   (OUT_BS + NBEAM)
#define OUT_BI   (OUT_RT + NBEAM)
#define OUT_LOSS (OUT_BI + NBEAM)

// Scratch (device globals — allocation-free)
__device__ float g_scores[B_ * E_];
__device__ float g_weight[NBEAM];
__device__ int   g_expert[NBEAM];
__device__ int   g_perm[NBEAM];
__device__ int   g_off[E_ + 1];
__device__ float g_xr[(size_t)B_ * T_ * H_];             // tf32-rounded x (6.3 MB)
__device__ float g_h[(size_t)NBEAM * T_ * DFF_];         // tf32-rounded h (50.3 MB)
__device__ float g_part[(size_t)SPLIT * NBEAM * T_ * H_];// split-K partials (50.3 MB)

// ---------------------------------------------------------------------------
// helpers
// ---------------------------------------------------------------------------
__device__ __forceinline__ uint32_t smem_u32(const void* p) {
    uint32_t a;
    asm("{ .reg .u64 t; cvta.to.shared.u64 t, %1; cvt.u32.u64 %0, t; }"
        : "=r"(a) : "l"(p));
    return a;
}

__device__ __forceinline__ void cp16(uint32_t smem_addr, const void* gptr) {
    asm volatile("cp.async.cg.shared.global [%0], [%1], 16;"
                 :: "r"(smem_addr), "l"(gptr));
}
#define CP_COMMIT() asm volatile("cp.async.commit_group;" ::: "memory")
#define CP_WAIT1()  asm volatile("cp.async.wait_group 1;" ::: "memory")

__device__ __forceinline__ uint32_t f2tf32(float f) {
    uint32_t r;
    asm("cvt.rna.tf32.f32 %0, %1;" : "=r"(r) : "f"(f));
    return r;
}
__device__ __forceinline__ float tf32r(float f) {
    return __uint_as_float(f2tf32(f));
}

__device__ __forceinline__ void mma1688(float* c, const uint32_t* a, const uint32_t* b) {
    asm volatile(
        "mma.sync.aligned.m16n8k8.row.col.f32.tf32.tf32.f32 "
        "{%0,%1,%2,%3}, {%4,%5,%6,%7}, {%8,%9}, {%0,%1,%2,%3};"
        : "+f"(c[0]), "+f"(c[1]), "+f"(c[2]), "+f"(c[3])
        : "r"(a[0]), "r"(a[1]), "r"(a[2]), "r"(a[3]), "r"(b[0]), "r"(b[1]));
}

__device__ __forceinline__ float gelu_exact(float v) {
    return 0.5f * v * (1.0f + erff(v * 0.70710678118654752f));
}

// ---------------------------------------------------------------------------
// prep: round x to tf32 values (so GEMM1 B-operand needs no in-loop cvt)
// ---------------------------------------------------------------------------
__global__ void prep_x_kernel(const float* __restrict__ x)
{
    int i = blockIdx.x * blockDim.x + threadIdx.x;   // float4 index
    const int N4 = B_ * T_ * H_ / 4;
    if (i >= N4) return;
    float4 v = ((const float4*)x)[i];
    v.x = tf32r(v.x); v.y = tf32r(v.y); v.z = tf32r(v.z); v.w = tf32r(v.w);
    ((float4*)g_xr)[i] = v;
}

// ---------------------------------------------------------------------------
// Kernel 1: gating — per-batch mean over T, logits, softmax
// ---------------------------------------------------------------------------
__global__ void gate_kernel(const float* __restrict__ x,
                            const float* __restrict__ gw)
{
    int b = blockIdx.x, tid = threadIdx.x;
    float part[E_];
#pragma unroll
    for (int e = 0; e < E_; e++) part[e] = 0.f;
    const float* xb = x + (size_t)b * T_ * H_;
    for (int h = tid; h < H_; h += 256) {
        float s = 0.f;
#pragma unroll 8
        for (int t = 0; t < T_; t++) s += xb[t * H_ + h];
        float avg = s * (1.f / (float)T_);
#pragma unroll
        for (int e = 0; e < E_; e++) part[e] += avg * gw[e * H_ + h];
    }
#pragma unroll
    for (int off = 16; off > 0; off >>= 1)
#pragma unroll
        for (int e = 0; e < E_; e++)
            part[e] += __shfl_down_sync(0xffffffffu, part[e], off);
    __shared__ float sacc[E_];
    if (tid < E_) sacc[tid] = 0.f;
    __syncthreads();
    if ((tid & 31) == 0)
#pragma unroll
        for (int e = 0; e < E_; e++) atomicAdd(&sacc[e], part[e]);
    __syncthreads();
    if (tid == 0) {
        float m = sacc[0];
#pragma unroll
        for (int e = 1; e < E_; e++) m = fmaxf(m, sacc[e]);
        float ex[E_], s = 0.f;
#pragma unroll
        for (int e = 0; e < E_; e++) { ex[e] = expf(sacc[e] - m); s += ex[e]; }
        float inv = 1.f / s;
#pragma unroll
        for (int e = 0; e < E_; e++) g_scores[b * E_ + e] = ex[e] * inv;
    }
}

// ---------------------------------------------------------------------------
// Kernel 2: finalize routing — top-2, loss, tail outputs, expert grouping
// ---------------------------------------------------------------------------
__global__ void finalize_kernel(float* __restrict__ out)
{
    int tid = threadIdx.x;
    __shared__ float simp[E_];
    if (tid < E_) {
        float s = 0.f;
        for (int b = 0; b < B_; b++) s += g_scores[b * E_ + tid];
        simp[tid] = s;
    }
    if (tid < B_) {
        int b = tid;
        float v0 = -1.f, v1 = -1.f; int i0 = 0, i1 = 0;
#pragma unroll
        for (int e = 0; e < E_; e++) {
            float v = g_scores[b * E_ + e];
            if (v > v0)      { v1 = v0; i1 = i0; v0 = v; i0 = e; }
            else if (v > v1) { v1 = v;  i1 = e; }
        }
        out[OUT_BS + 2 * b]     = v0;
        out[OUT_BS + 2 * b + 1] = v1;
        out[OUT_RT + 2 * b]     = (float)i0;
        out[OUT_RT + 2 * b + 1] = (float)i1;
        g_weight[2 * b] = v0;  g_weight[2 * b + 1] = v1;
        g_expert[2 * b] = i0;  g_expert[2 * b + 1] = i1;
    }
    out[OUT_BI + tid] = (float)tid;
    __syncthreads();
    if (tid == 0) {
        float mean = 0.f;
#pragma unroll
        for (int e = 0; e < E_; e++) mean += simp[e];
        mean *= (1.f / (float)E_);
        float var = 0.f;
#pragma unroll
        for (int e = 0; e < E_; e++) { float d = simp[e] - mean; var += d * d; }
        var *= (1.f / (float)(E_ - 1));
        out[OUT_LOSS] = var / (mean * mean);
        int pos = 0;
        for (int e = 0; e < E_; e++) {
            g_off[e] = pos;
            for (int bm = 0; bm < NBEAM; bm++)
                if (g_expert[bm] == e) g_perm[pos++] = bm;
        }
        g_off[E_] = pos;
    }
}

// ---------------------------------------------------------------------------
// Shared GEMM geometry: CTA M=64 x N=128, BK=16, 256 thr, 8 warps (4x2),
// warp tile 16x64, 3-stage cp.async pipeline.
// ---------------------------------------------------------------------------
#define BM 64
#define BN 128
#define BKT 16
#define STG 3
#define STR 20
#define ABUF (BM * STR)
#define BBUF (BN * STR)
#define SMEM_FLOATS (STG * (ABUF + BBUF))

// GEMM1: h = gelu(x @ W1^T + b1), stored tf32-rounded.
// grid (DFF/64=48, E, 32 chunk-slots)
__global__ void __launch_bounds__(256, 3)
gemm1_kernel(const float* __restrict__ W, const float* __restrict__ bias)
{
    const int e = blockIdx.y;
    const int cnt = g_off[e + 1] - g_off[e];
    const int chunk = blockIdx.z;
    if (chunk * 4 >= cnt) return;
    const int m0 = blockIdx.x * BM;

    extern __shared__ __align__(16) float smem[];
    float* As = smem;
    float* Bs = smem + STG * ABUF;

    const int tid = threadIdx.x;
    const int wid = tid >> 5, lane = tid & 31;
    const int wm = wid >> 1, wn = wid & 1;
    const int lg = lane >> 2, lt = lane & 3;

    int beamv[4];
#pragma unroll
    for (int j = 0; j < 4; j++) {
        int idx = chunk * 4 + j;
        beamv[j] = (idx < cnt) ? g_perm[g_off[e] + idx] : -1;
    }

    const float* wbase = W + (size_t)e * DFF_ * H_;
    const float* agp;  uint32_t asp;
    const float* bgp[2]; uint32_t bsp[2];
    {
        int row = tid >> 2, c = tid & 3;
        agp = wbase + (size_t)(m0 + row) * H_ + c * 4;
        asp = smem_u32(As) + (uint32_t)(row * STR + c * 4) * 4u;
    }
#pragma unroll
    for (int t = 0; t < 2; t++) {
        int id = tid + 256 * t;
        int tok = id >> 2, c = id & 3;
        int slot = tok >> 5, tt = tok & 31;
        int bm = beamv[slot]; if (bm < 0) bm = beamv[0];
        bgp[t] = g_xr + ((size_t)(bm >> 1) * T_ + tt) * H_ + c * 4;
        bsp[t] = smem_u32(Bs) + (uint32_t)(tok * STR + c * 4) * 4u;
    }

    const uint32_t ABUFB = ABUF * 4u, BBUFB = BBUF * 4u;
    const int KT = H_ / BKT;   // 48

#pragma unroll
    for (int s = 0; s < 2; s++) {
        cp16(asp + s * ABUFB, agp + s * BKT);
#pragma unroll
        for (int t = 0; t < 2; t++) cp16(bsp[t] + s * BBUFB, bgp[t] + s * BKT);
        CP_COMMIT();
    }

    float acc[8][4];
#pragma unroll
    for (int j = 0; j < 8; j++)
#pragma unroll
        for (int r = 0; r < 4; r++) acc[j][r] = 0.f;

    int buf = 0, pbuf = 2;
#pragma unroll 1
    for (int kt = 0; kt < KT; kt++) {
        CP_WAIT1();
        __syncthreads();
        if (kt + 2 < KT) {
            int koff = (kt + 2) * BKT;
            cp16(asp + pbuf * ABUFB, agp + koff);
#pragma unroll
            for (int t = 0; t < 2; t++) cp16(bsp[t] + pbuf * BBUFB, bgp[t] + koff);
        }
        CP_COMMIT();

        const float* Ab = As + buf * ABUF;
        const float* Bb = Bs + buf * BBUF;
#pragma unroll
        for (int ks = 0; ks < 2; ks++) {
            const int kc = ks * 8 + lt;
            uint32_t afr[4], bfr[8][2];
            {
                int r = wm * 16 + lg;
                afr[0] = f2tf32(Ab[r * STR + kc]);
                afr[1] = f2tf32(Ab[(r + 8) * STR + kc]);
                afr[2] = f2tf32(Ab[r * STR + kc + 4]);
                afr[3] = f2tf32(Ab[(r + 8) * STR + kc + 4]);
            }
#pragma unroll
            for (int j = 0; j < 8; j++) {
                int n = wn * 64 + j * 8 + lg;
                bfr[j][0] = __float_as_uint(Bb[n * STR + kc]);       // pre-rounded
                bfr[j][1] = __float_as_uint(Bb[n * STR + kc + 4]);
            }
#pragma unroll
            for (int j = 0; j < 8; j++) mma1688(acc[j], afr, bfr[j]);
        }
        buf = (buf == STG - 1) ? 0 : buf + 1;
        pbuf = (pbuf == STG - 1) ? 0 : pbuf + 1;
    }

    // epilogue: gelu(+bias), round to tf32, store
    {
        int r0 = wm * 16 + lg, r1 = r0 + 8;
        int gm0 = m0 + r0, gm1 = m0 + r1;
        float bi0 = bias[e * DFF_ + gm0];
        float bi1 = bias[e * DFF_ + gm1];
#pragma unroll
        for (int j = 0; j < 8; j++) {
            int tok = wn * 64 + j * 8 + lt * 2;
            int bm = beamv[tok >> 5];
            if (bm < 0) continue;
            int tt = tok & 31;
            float* p = g_h + ((size_t)bm * T_ + tt) * DFF_;
            p[gm0]        = tf32r(gelu_exact(acc[j][0] + bi0));
            p[DFF_ + gm0] = tf32r(gelu_exact(acc[j][1] + bi0));
            p[gm1]        = tf32r(gelu_exact(acc[j][2] + bi1));
            p[DFF_ + gm1] = tf32r(gelu_exact(acc[j][3] + bi1));
        }
    }
}

// GEMM2 split-K: partial = h @ W2^T over K-slice, raw acc -> g_part
// grid (H/64=12, E, 32 chunk-slots * SPLIT);  z = chunk*SPLIT + split
__global__ void __launch_bounds__(256, 3)
gemm2_kernel(const float* __restrict__ W)
{
    const int e = blockIdx.y;
    const int cnt = g_off[e + 1] - g_off[e];
    const int chunk = blockIdx.z / SPLIT;
    const int split = blockIdx.z % SPLIT;
    if (chunk * 4 >= cnt) return;
    const int m0 = blockIdx.x * BM;
    const int k0 = split * (DFF_ / SPLIT);   // 768-float K-slice

    extern __shared__ __align__(16) float smem[];
    float* As = smem;
    float* Bs = smem + STG * ABUF;

    const int tid = threadIdx.x;
    const int wid = tid >> 5, lane = tid & 31;
    const int wm = wid >> 1, wn = wid & 1;
    const int lg = lane >> 2, lt = lane & 3;

    int beamv[4];
#pragma unroll
    for (int j = 0; j < 4; j++) {
        int idx = chunk * 4 + j;
        beamv[j] = (idx < cnt) ? g_perm[g_off[e] + idx] : -1;
    }

    const float* wbase = W + (size_t)e * H_ * DFF_ + k0;
    const float* agp;  uint32_t asp;
    const float* bgp[2]; uint32_t bsp[2];
    {
        int row = tid >> 2, c = tid & 3;
        agp = wbase + (size_t)(m0 + row) * DFF_ + c * 4;
        asp = smem_u32(As) + (uint32_t)(row * STR + c * 4) * 4u;
    }
#pragma unroll
    for (int t = 0; t < 2; t++) {
        int id = tid + 256 * t;
        int tok = id >> 2, c = id & 3;
        int slot = tok >> 5, tt = tok & 31;
        int bm = beamv[slot]; if (bm < 0) bm = beamv[0];
        bgp[t] = g_h + ((size_t)bm * T_ + tt) * DFF_ + k0 + c * 4;
        bsp[t] = smem_u32(Bs) + (uint32_t)(tok * STR + c * 4) * 4u;
    }

    const uint32_t ABUFB = ABUF * 4u, BBUFB = BBUF * 4u;
    const int KT = (DFF_ / SPLIT) / BKT;   // 48

#pragma unroll
    for (int s = 0; s < 2; s++) {
        cp16(asp + s * ABUFB, agp + s * BKT);
#pragma unroll
        for (int t = 0; t < 2; t++) cp16(bsp[t] + s * BBUFB, bgp[t] + s * BKT);
        CP_COMMIT();
    }

    float acc[8][4];
#pragma unroll
    for (int j = 0; j < 8; j++)
#pragma unroll
        for (int r = 0; r < 4; r++) acc[j][r] = 0.f;

    int buf = 0, pbuf = 2;
#pragma unroll 1
    for (int kt = 0; kt < KT; kt++) {
        CP_WAIT1();
        __syncthreads();
        if (kt + 2 < KT) {
            int koff = (kt + 2) * BKT;
            cp16(asp + pbuf * ABUFB, agp + koff);
#pragma unroll
            for (int t = 0; t < 2; t++) cp16(bsp[t] + pbuf * BBUFB, bgp[t] + koff);
        }
        CP_COMMIT();

        const float* Ab = As + buf * ABUF;
        const float* Bb = Bs + buf * BBUF;
#pragma unroll
        for (int ks = 0; ks < 2; ks++) {
            const int kc = ks * 8 + lt;
            uint32_t afr[4], bfr[8][2];
            {
                int r = wm * 16 + lg;
                afr[0] = f2tf32(Ab[r * STR + kc]);
                afr[1] = f2tf32(Ab[(r + 8) * STR + kc]);
                afr[2] = f2tf32(Ab[r * STR + kc + 4]);
                afr[3] = f2tf32(Ab[(r + 8) * STR + kc + 4]);
            }
#pragma unroll
            for (int j = 0; j < 8; j++) {
                int n = wn * 64 + j * 8 + lg;
                bfr[j][0] = __float_as_uint(Bb[n * STR + kc]);       // pre-rounded
                bfr[j][1] = __float_as_uint(Bb[n * STR + kc + 4]);
            }
#pragma unroll
            for (int j = 0; j < 8; j++) mma1688(acc[j], afr, bfr[j]);
        }
        buf = (buf == STG - 1) ? 0 : buf + 1;
        pbuf = (pbuf == STG - 1) ? 0 : pbuf + 1;
    }

    // epilogue: raw partial -> g_part[split]
    {
        int r0 = wm * 16 + lg, r1 = r0 + 8;
        int gm0 = m0 + r0, gm1 = m0 + r1;
        float* pb = g_part + (size_t)split * NBEAM * T_ * H_;
#pragma unroll
        for (int j = 0; j < 8; j++) {
            int tok = wn * 64 + j * 8 + lt * 2;
            int bm = beamv[tok >> 5];
            if (bm < 0) continue;
            int tt = tok & 31;
            float* p = pb + ((size_t)bm * T_ + tt) * H_;
            p[gm0]      = acc[j][0];
            p[H_ + gm0] = acc[j][1];
            p[gm1]      = acc[j][2];
            p[H_ + gm1] = acc[j][3];
        }
    }
}

// Reduce: out = (sum_splits + b2[e]) * wgt
__global__ void reduce_kernel(const float* __restrict__ b2, float* __restrict__ out)
{
    int i = blockIdx.x * blockDim.x + threadIdx.x;   // float4 index
    const int N4 = NBEAM * T_ * H_ / 4;
    if (i >= N4) return;
    int flat = i * 4;
    int beam = flat / (T_ * H_);
    int hh   = flat % H_;
    int e    = g_expert[beam];
    float wgt = g_weight[beam];
    const size_t PS = (size_t)NBEAM * T_ * H_;
    float4 s = ((const float4*)g_part)[i];
    float4 p1 = ((const float4*)(g_part + PS))[i];
    float4 p2 = ((const float4*)(g_part + 2 * PS))[i];
    float4 p3 = ((const float4*)(g_part + 3 * PS))[i];
    float4 bb = *(const float4*)(b2 + e * H_ + hh);
    float4 o;
    o.x = (s.x + p1.x + p2.x + p3.x + bb.x) * wgt;
    o.y = (s.y + p1.y + p2.y + p3.y + bb.y) * wgt;
    o.z = (s.z + p1.z + p2.z + p3.z + bb.z) * wgt;
    o.w = (s.w + p1.w + p2.w + p3.w + bb.w) * wgt;
    ((float4*)(out + OUT_MAIN))[i] = o;
}

// ---------------------------------------------------------------------------
extern "C" void kernel_launch(void* const* d_in, const int* in_sizes, int n_in,
                              void* d_out, int out_size)
{
    (void)in_sizes; (void)n_in; (void)out_size;
    const float* x      = (const float*)d_in[0];
    const float* gate_w = (const float*)d_in[1];
    const float* w1     = (const float*)d_in[2];
    const float* b1     = (const float*)d_in[3];
    const float* w2     = (const float*)d_in[4];
    const float* b2     = (const float*)d_in[5];
    float* out = (float*)d_out;

    const int smem_bytes = SMEM_FLOATS * 4;   // 46080

    prep_x_kernel<<<(B_ * T_ * H_ / 4 + 255) / 256, 256>>>(x);
    gate_kernel<<<B_, 256>>>(x, gate_w);
    finalize_kernel<<<1, 128>>>(out);
    gemm1_kernel<<<dim3(DFF_ / BM, E_, 32), 256, smem_bytes>>>(w1, b1);
    gemm2_kernel<<<dim3(H_ / BM, E_, 32 * SPLIT), 256, smem_bytes>>>(w2);
    reduce_kernel<<<(NBEAM * T_ * H_ / 4 + 255) / 256, 256>>>(b2, out);
}

// round 7
// speedup vs baseline: 3.0448x; 1.2066x over previous
#include <cuda_runtime.h>
#include <math.h>
#include <stdint.h>

// Problem constants
#define B_   64
#define T_   32
#define H_   768
#define E_   8
#define NB_  2
#define DFF_ 3072
#define NBEAM 128   // B*NB
#define SPLIT 4     // split-K factor for GEMM2

// Output packing offsets (float32 concatenation in tuple order)
#define OUT_MAIN 0
#define OUT_BS   (NBEAM * T_ * H_)        // 3145728
#define OUT_RT   (OUT_BS + NBEAM)
#define OUT_BI   (OUT_RT + NBEAM)
#define OUT_LOSS (OUT_BI + NBEAM)

// Scratch (device globals — allocation-free)
__device__ float g_scores[B_ * E_];
__device__ float g_weight[NBEAM];
__device__ int   g_expert[NBEAM];
__device__ int   g_perm[NBEAM];
__device__ int   g_off[E_ + 1];
__device__ float g_xr[(size_t)B_ * T_ * H_];             // tf32-rounded x
__device__ float g_h[(size_t)NBEAM * T_ * DFF_];         // tf32-rounded h
__device__ float g_part[(size_t)SPLIT * NBEAM * T_ * H_];// split-K partials

// ---------------------------------------------------------------------------
// helpers
// ---------------------------------------------------------------------------
__device__ __forceinline__ uint32_t smem_u32(const void* p) {
    uint32_t a;
    asm("{ .reg .u64 t; cvta.to.shared.u64 t, %1; cvt.u32.u64 %0, t; }"
        : "=r"(a) : "l"(p));
    return a;
}

__device__ __forceinline__ void cp16(uint32_t smem_addr, const void* gptr) {
    asm volatile("cp.async.cg.shared.global [%0], [%1], 16;"
                 :: "r"(smem_addr), "l"(gptr));
}
#define CP_COMMIT() asm volatile("cp.async.commit_group;" ::: "memory")
#define CP_WAIT1()  asm volatile("cp.async.wait_group 1;" ::: "memory")

__device__ __forceinline__ uint32_t f2tf32(float f) {
    uint32_t r;
    asm("cvt.rna.tf32.f32 %0, %1;" : "=r"(r) : "f"(f));
    return r;
}
__device__ __forceinline__ float tf32r(float f) {
    return __uint_as_float(f2tf32(f));
}

// ldmatrix x4: loads 4 8x8 b16 matrices (= 16 rows x 8 f32-cols region with
// address map row = R0 + (t&15), col = C0 + (t>>4)*4)
__device__ __forceinline__ void ldsm4(uint32_t* r, uint32_t addr) {
    asm volatile("ldmatrix.sync.aligned.m8n8.x4.shared.b16 {%0,%1,%2,%3}, [%4];"
        : "=r"(r[0]), "=r"(r[1]), "=r"(r[2]), "=r"(r[3]) : "r"(addr));
}

__device__ __forceinline__ void mma1688(float* c, const uint32_t* a, const uint32_t* b) {
    asm volatile(
        "mma.sync.aligned.m16n8k8.row.col.f32.tf32.tf32.f32 "
        "{%0,%1,%2,%3}, {%4,%5,%6,%7}, {%8,%9}, {%0,%1,%2,%3};"
        : "+f"(c[0]), "+f"(c[1]), "+f"(c[2]), "+f"(c[3])
        : "r"(a[0]), "r"(a[1]), "r"(a[2]), "r"(a[3]), "r"(b[0]), "r"(b[1]));
}

__device__ __forceinline__ float gelu_exact(float v) {
    return 0.5f * v * (1.0f + erff(v * 0.70710678118654752f));
}

// ---------------------------------------------------------------------------
// prep: round x to tf32 (GEMM1 B-operand then needs no cvt)
// ---------------------------------------------------------------------------
__global__ void prep_x_kernel(const float* __restrict__ x)
{
    int i = blockIdx.x * blockDim.x + threadIdx.x;
    const int N4 = B_ * T_ * H_ / 4;
    if (i >= N4) return;
    float4 v = ((const float4*)x)[i];
    v.x = tf32r(v.x); v.y = tf32r(v.y); v.z = tf32r(v.z); v.w = tf32r(v.w);
    ((float4*)g_xr)[i] = v;
}

// ---------------------------------------------------------------------------
// gating
// ---------------------------------------------------------------------------
__global__ void gate_kernel(const float* __restrict__ x,
                            const float* __restrict__ gw)
{
    int b = blockIdx.x, tid = threadIdx.x;
    float part[E_];
#pragma unroll
    for (int e = 0; e < E_; e++) part[e] = 0.f;
    const float* xb = x + (size_t)b * T_ * H_;
    for (int h = tid; h < H_; h += 256) {
        float s = 0.f;
#pragma unroll 8
        for (int t = 0; t < T_; t++) s += xb[t * H_ + h];
        float avg = s * (1.f / (float)T_);
#pragma unroll
        for (int e = 0; e < E_; e++) part[e] += avg * gw[e * H_ + h];
    }
#pragma unroll
    for (int off = 16; off > 0; off >>= 1)
#pragma unroll
        for (int e = 0; e < E_; e++)
            part[e] += __shfl_down_sync(0xffffffffu, part[e], off);
    __shared__ float sacc[E_];
    if (tid < E_) sacc[tid] = 0.f;
    __syncthreads();
    if ((tid & 31) == 0)
#pragma unroll
        for (int e = 0; e < E_; e++) atomicAdd(&sacc[e], part[e]);
    __syncthreads();
    if (tid == 0) {
        float m = sacc[0];
#pragma unroll
        for (int e = 1; e < E_; e++) m = fmaxf(m, sacc[e]);
        float ex[E_], s = 0.f;
#pragma unroll
        for (int e = 0; e < E_; e++) { ex[e] = expf(sacc[e] - m); s += ex[e]; }
        float inv = 1.f / s;
#pragma unroll
        for (int e = 0; e < E_; e++) g_scores[b * E_ + e] = ex[e] * inv;
    }
}

// ---------------------------------------------------------------------------
// finalize routing
// ---------------------------------------------------------------------------
__global__ void finalize_kernel(float* __restrict__ out)
{
    int tid = threadIdx.x;
    __shared__ float simp[E_];
    if (tid < E_) {
        float s = 0.f;
        for (int b = 0; b < B_; b++) s += g_scores[b * E_ + tid];
        simp[tid] = s;
    }
    if (tid < B_) {
        int b = tid;
        float v0 = -1.f, v1 = -1.f; int i0 = 0, i1 = 0;
#pragma unroll
        for (int e = 0; e < E_; e++) {
            float v = g_scores[b * E_ + e];
            if (v > v0)      { v1 = v0; i1 = i0; v0 = v; i0 = e; }
            else if (v > v1) { v1 = v;  i1 = e; }
        }
        out[OUT_BS + 2 * b]     = v0;
        out[OUT_BS + 2 * b + 1] = v1;
        out[OUT_RT + 2 * b]     = (float)i0;
        out[OUT_RT + 2 * b + 1] = (float)i1;
        g_weight[2 * b] = v0;  g_weight[2 * b + 1] = v1;
        g_expert[2 * b] = i0;  g_expert[2 * b + 1] = i1;
    }
    out[OUT_BI + tid] = (float)tid;
    __syncthreads();
    if (tid == 0) {
        float mean = 0.f;
#pragma unroll
        for (int e = 0; e < E_; e++) mean += simp[e];
        mean *= (1.f / (float)E_);
        float var = 0.f;
#pragma unroll
        for (int e = 0; e < E_; e++) { float d = simp[e] - mean; var += d * d; }
        var *= (1.f / (float)(E_ - 1));
        out[OUT_LOSS] = var / (mean * mean);
        int pos = 0;
        for (int e = 0; e < E_; e++) {
            g_off[e] = pos;
            for (int bm = 0; bm < NBEAM; bm++)
                if (g_expert[bm] == e) g_perm[pos++] = bm;
        }
        g_off[E_] = pos;
    }
}

// ---------------------------------------------------------------------------
// GEMM geometry: CTA 64(M) x 128(N tokens), BK=16, 128 thr, 4 warps (2x2),
// warp tile 32x64 via ldmatrix, 3-stage cp.async pipeline.
// ---------------------------------------------------------------------------
#define BM 64
#define BN 128
#define BKT 16
#define STG 3
#define STR 20
#define ABUF (BM * STR)           // 1280 floats
#define BBUF (BN * STR)           // 2560 floats
#define SMEM_FLOATS (STG * (ABUF + BBUF))   // 11520 = 46080 B
#define ABUFB (ABUF * 4u)
#define BBUFB (BBUF * 4u)

// core mainloop body shared by both GEMMs (A needs cvt; B pre-rounded)
#define GEMM_MAINLOOP(KT_)                                                     \
    int buf = 0, pbuf = 2;                                                     \
    _Pragma("unroll 1")                                                        \
    for (int kt = 0; kt < (KT_); kt++) {                                       \
        CP_WAIT1();                                                            \
        __syncthreads();                                                       \
        if (kt + 2 < (KT_)) {                                                  \
            int koff = (kt + 2) * BKT;                                         \
            cp16(asp[0] + pbuf * ABUFB, agp[0] + koff);                        \
            cp16(asp[1] + pbuf * ABUFB, agp[1] + koff);                        \
            _Pragma("unroll")                                                  \
            for (int t = 0; t < 4; t++)                                        \
                cp16(bsp[t] + pbuf * BBUFB, bgp[t] + koff);                    \
        }                                                                      \
        CP_COMMIT();                                                           \
        _Pragma("unroll")                                                      \
        for (int ks = 0; ks < 2; ks++) {                                       \
            uint32_t ab = a_base + buf * ABUFB + ks * 32;                      \
            uint32_t bb = b_base + buf * BBUFB + ks * 32;                      \
            uint32_t ar0[4], ar1[4];                                           \
            ldsm4(ar0, ab);                                                    \
            ldsm4(ar1, ab + 16 * STR * 4);                                     \
            uint32_t br[4][4];                                                 \
            _Pragma("unroll")                                                  \
            for (int jj = 0; jj < 4; jj++)                                     \
                ldsm4(br[jj], bb + jj * 16 * STR * 4);                         \
            uint32_t af0[4], af1[4];                                           \
            _Pragma("unroll")                                                  \
            for (int q = 0; q < 4; q++) {                                      \
                af0[q] = f2tf32(__uint_as_float(ar0[q]));                      \
                af1[q] = f2tf32(__uint_as_float(ar1[q]));                      \
            }                                                                  \
            _Pragma("unroll")                                                  \
            for (int jj = 0; jj < 4; jj++) {                                   \
                uint32_t b0[2] = { br[jj][0], br[jj][2] };                     \
                uint32_t b1[2] = { br[jj][1], br[jj][3] };                     \
                mma1688(acc[0][2 * jj],     af0, b0);                          \
                mma1688(acc[1][2 * jj],     af1, b0);                          \
                mma1688(acc[0][2 * jj + 1], af0, b1);                          \
                mma1688(acc[1][2 * jj + 1], af1, b1);                          \
            }                                                                  \
        }                                                                      \
        buf = (buf == STG - 1) ? 0 : buf + 1;                                  \
        pbuf = (pbuf == STG - 1) ? 0 : pbuf + 1;                               \
    }

// GEMM1: h = gelu(x @ W1^T + b1) stored tf32-rounded.  grid (48, E, 32)
__global__ void __launch_bounds__(128, 4)
gemm1_kernel(const float* __restrict__ W, const float* __restrict__ bias)
{
    const int e = blockIdx.y;
    const int cnt = g_off[e + 1] - g_off[e];
    const int chunk = blockIdx.z;
    if (chunk * 4 >= cnt) return;
    const int m0 = blockIdx.x * BM;

    extern __shared__ __align__(16) float smem[];
    float* As = smem;
    float* Bs = smem + STG * ABUF;

    const int tid = threadIdx.x;
    const int wid = tid >> 5, lane = tid & 31;
    const int wm = wid >> 1, wn = wid & 1;
    const int lg = lane >> 2, lt = lane & 3;

    int beamv[4];
#pragma unroll
    for (int j = 0; j < 4; j++) {
        int idx = chunk * 4 + j;
        beamv[j] = (idx < cnt) ? g_perm[g_off[e] + idx] : -1;
    }

    // cp.async coords: A 64x16 = 256 f4 (2/thr); B 128x16 = 512 f4 (4/thr)
    const float* wbase = W + (size_t)e * DFF_ * H_;
    const float* agp[2]; uint32_t asp[2];
    const float* bgp[4]; uint32_t bsp[4];
#pragma unroll
    for (int t = 0; t < 2; t++) {
        int id = tid + 128 * t;
        int row = id >> 2, c = id & 3;
        agp[t] = wbase + (size_t)(m0 + row) * H_ + c * 4;
        asp[t] = smem_u32(As) + (uint32_t)(row * STR + c * 4) * 4u;
    }
#pragma unroll
    for (int t = 0; t < 4; t++) {
        int id = tid + 128 * t;
        int tok = id >> 2, c = id & 3;
        int slot = tok >> 5, tt = tok & 31;
        int bm = beamv[slot]; if (bm < 0) bm = beamv[0];
        bgp[t] = g_xr + ((size_t)(bm >> 1) * T_ + tt) * H_ + c * 4;
        bsp[t] = smem_u32(Bs) + (uint32_t)(tok * STR + c * 4) * 4u;
    }

    // ldmatrix bases: row = base + (lane&15), col = (lane>>4)*4
    const uint32_t a_base = smem_u32(As)
        + (uint32_t)(((wm * 32 + (lane & 15)) * STR + ((lane >> 4) << 2)) << 2);
    const uint32_t b_base = smem_u32(Bs)
        + (uint32_t)(((wn * 64 + (lane & 15)) * STR + ((lane >> 4) << 2)) << 2);

    const int KT = H_ / BKT;   // 48

#pragma unroll
    for (int s = 0; s < 2; s++) {
        cp16(asp[0] + s * ABUFB, agp[0] + s * BKT);
        cp16(asp[1] + s * ABUFB, agp[1] + s * BKT);
#pragma unroll
        for (int t = 0; t < 4; t++) cp16(bsp[t] + s * BBUFB, bgp[t] + s * BKT);
        CP_COMMIT();
    }

    float acc[2][8][4];
#pragma unroll
    for (int i = 0; i < 2; i++)
#pragma unroll
        for (int j = 0; j < 8; j++)
#pragma unroll
            for (int r = 0; r < 4; r++) acc[i][j][r] = 0.f;

    GEMM_MAINLOOP(KT)

    // epilogue: gelu(+bias), tf32-round, store
#pragma unroll
    for (int i = 0; i < 2; i++) {
        int r0 = wm * 32 + i * 16 + lg, r1 = r0 + 8;
        int gm0 = m0 + r0, gm1 = m0 + r1;
        float bi0 = bias[e * DFF_ + gm0];
        float bi1 = bias[e * DFF_ + gm1];
#pragma unroll
        for (int j = 0; j < 8; j++) {
            int tok = wn * 64 + j * 8 + lt * 2;
            int bm = beamv[tok >> 5];
            if (bm < 0) continue;
            int tt = tok & 31;
            float* p = g_h + ((size_t)bm * T_ + tt) * DFF_;
            p[gm0]        = tf32r(gelu_exact(acc[i][j][0] + bi0));
            p[DFF_ + gm0] = tf32r(gelu_exact(acc[i][j][1] + bi0));
            p[gm1]        = tf32r(gelu_exact(acc[i][j][2] + bi1));
            p[DFF_ + gm1] = tf32r(gelu_exact(acc[i][j][3] + bi1));
        }
    }
}

// GEMM2 split-K: partial = h @ W2^T over K-slice -> g_part. grid (12, E, 32*SPLIT)
__global__ void __launch_bounds__(128, 4)
gemm2_kernel(const float* __restrict__ W)
{
    const int e = blockIdx.y;
    const int cnt = g_off[e + 1] - g_off[e];
    const int chunk = blockIdx.z / SPLIT;
    const int split = blockIdx.z % SPLIT;
    if (chunk * 4 >= cnt) return;
    const int m0 = blockIdx.x * BM;
    const int k0 = split * (DFF_ / SPLIT);

    extern __shared__ __align__(16) float smem[];
    float* As = smem;
    float* Bs = smem + STG * ABUF;

    const int tid = threadIdx.x;
    const int wid = tid >> 5, lane = tid & 31;
    const int wm = wid >> 1, wn = wid & 1;
    const int lg = lane >> 2, lt = lane & 3;

    int beamv[4];
#pragma unroll
    for (int j = 0; j < 4; j++) {
        int idx = chunk * 4 + j;
        beamv[j] = (idx < cnt) ? g_perm[g_off[e] + idx] : -1;
    }

    const float* wbase = W + (size_t)e * H_ * DFF_ + k0;
    const float* agp[2]; uint32_t asp[2];
    const float* bgp[4]; uint32_t bsp[4];
#pragma unroll
    for (int t = 0; t < 2; t++) {
        int id = tid + 128 * t;
        int row = id >> 2, c = id & 3;
        agp[t] = wbase + (size_t)(m0 + row) * DFF_ + c * 4;
        asp[t] = smem_u32(As) + (uint32_t)(row * STR + c * 4) * 4u;
    }
#pragma unroll
    for (int t = 0; t < 4; t++) {
        int id = tid + 128 * t;
        int tok = id >> 2, c = id & 3;
        int slot = tok >> 5, tt = tok & 31;
        int bm = beamv[slot]; if (bm < 0) bm = beamv[0];
        bgp[t] = g_h + ((size_t)bm * T_ + tt) * DFF_ + k0 + c * 4;
        bsp[t] = smem_u32(Bs) + (uint32_t)(tok * STR + c * 4) * 4u;
    }

    const uint32_t a_base = smem_u32(As)
        + (uint32_t)(((wm * 32 + (lane & 15)) * STR + ((lane >> 4) << 2)) << 2);
    const uint32_t b_base = smem_u32(Bs)
        + (uint32_t)(((wn * 64 + (lane & 15)) * STR + ((lane >> 4) << 2)) << 2);

    const int KT = (DFF_ / SPLIT) / BKT;   // 48

#pragma unroll
    for (int s = 0; s < 2; s++) {
        cp16(asp[0] + s * ABUFB, agp[0] + s * BKT);
        cp16(asp[1] + s * ABUFB, agp[1] + s * BKT);
#pragma unroll
        for (int t = 0; t < 4; t++) cp16(bsp[t] + s * BBUFB, bgp[t] + s * BKT);
        CP_COMMIT();
    }

    float acc[2][8][4];
#pragma unroll
    for (int i = 0; i < 2; i++)
#pragma unroll
        for (int j = 0; j < 8; j++)
#pragma unroll
            for (int r = 0; r < 4; r++) acc[i][j][r] = 0.f;

    GEMM_MAINLOOP(KT)

    // epilogue: raw partials
#pragma unroll
    for (int i = 0; i < 2; i++) {
        int r0 = wm * 32 + i * 16 + lg, r1 = r0 + 8;
        int gm0 = m0 + r0, gm1 = m0 + r1;
        float* pb = g_part + (size_t)split * NBEAM * T_ * H_;
#pragma unroll
        for (int j = 0; j < 8; j++) {
            int tok = wn * 64 + j * 8 + lt * 2;
            int bm = beamv[tok >> 5];
            if (bm < 0) continue;
            int tt = tok & 31;
            float* p = pb + ((size_t)bm * T_ + tt) * H_;
            p[gm0]      = acc[i][j][0];
            p[H_ + gm0] = acc[i][j][1];
            p[gm1]      = acc[i][j][2];
            p[H_ + gm1] = acc[i][j][3];
        }
    }
}

// Reduce: out = (sum_splits + b2[e]) * wgt
__global__ void reduce_kernel(const float* __restrict__ b2, float* __restrict__ out)
{
    int i = blockIdx.x * blockDim.x + threadIdx.x;
    const int N4 = NBEAM * T_ * H_ / 4;
    if (i >= N4) return;
    int flat = i * 4;
    int beam = flat / (T_ * H_);
    int hh   = flat % H_;
    int e    = g_expert[beam];
    float wgt = g_weight[beam];
    const size_t PS = (size_t)NBEAM * T_ * H_;
    float4 s  = ((const float4*)g_part)[i];
    float4 p1 = ((const float4*)(g_part + PS))[i];
    float4 p2 = ((const float4*)(g_part + 2 * PS))[i];
    float4 p3 = ((const float4*)(g_part + 3 * PS))[i];
    float4 bb = *(const float4*)(b2 + e * H_ + hh);
    float4 o;
    o.x = (s.x + p1.x + p2.x + p3.x + bb.x) * wgt;
    o.y = (s.y + p1.y + p2.y + p3.y + bb.y) * wgt;
    o.z = (s.z + p1.z + p2.z + p3.z + bb.z) * wgt;
    o.w = (s.w + p1.w + p2.w + p3.w + bb.w) * wgt;
    ((float4*)(out + OUT_MAIN))[i] = o;
}

// ---------------------------------------------------------------------------
extern "C" void kernel_launch(void* const* d_in, const int* in_sizes, int n_in,
                              void* d_out, int out_size)
{
    (void)in_sizes; (void)n_in; (void)out_size;
    const float* x      = (const float*)d_in[0];
    const float* gate_w = (const float*)d_in[1];
    const float* w1     = (const float*)d_in[2];
    const float* b1     = (const float*)d_in[3];
    const float* w2     = (const float*)d_in[4];
    const float* b2     = (const float*)d_in[5];
    float* out = (float*)d_out;

    const int smem_bytes = SMEM_FLOATS * 4;   // 46080

    prep_x_kernel<<<(B_ * T_ * H_ / 4 + 255) / 256, 256>>>(x);
    gate_kernel<<<B_, 256>>>(x, gate_w);
    finalize_kernel<<<1, 128>>>(out);
    gemm1_kernel<<<dim3(DFF_ / BM, E_, 32), 128, smem_bytes>>>(w1, b1);
    gemm2_kernel<<<dim3(H_ / BM, E_, 32 * SPLIT), 128, smem_bytes>>>(w2);
    reduce_kernel<<<(NBEAM * T_ * H_ / 4 + 255) / 256, 256>>>(b2, out);
}